// round 7
// baseline (speedup 1.0000x reference)
#include <cuda_runtime.h>
#include <math.h>

#define N_CRIT   128
#define N_PAIRS  8128          // 128*127/2
#define N_TOT    8256          // N_CRIT + N_PAIRS
#define N_VEC4   2064          // N_TOT / 4
#define N_HALF4  1032          // half a row in float4
#define BATCH    16384
#define MIN_W    1e-7f
#define THREADS  512
#define ROWS_PER_BLOCK 8       // 16 warps: 2 warps per row (half-row each)

__device__ float g_w[N_TOT];   // constrained weights (wc_eff ‖ wint_eff)
__device__ float g_sum;        // total weight sum (zeroed via memset each launch)

// ---------------------------------------------------------------------------
// Prep: one pair per thread; block-partial sums atomicAdd'd into g_sum.
// grid = 32 blocks x 256 threads (8192 >= 8128).
// ---------------------------------------------------------------------------
__global__ __launch_bounds__(256)
void prep_weights_kernel(const float* __restrict__ wc,
                         const float* __restrict__ wint) {
    __shared__ float s_wc[N_CRIT];
    __shared__ float s_red[256];

    const int tid = threadIdx.x;
    float local = 0.0f;

    if (tid < N_CRIT) {
        float w = wc[tid];
        w = (w < 0.0f) ? MIN_W : w;
        s_wc[tid] = w;
        if (blockIdx.x == 0) {          // block 0 owns the wc part
            g_w[tid] = w;
            local += w;
        }
    }
    __syncthreads();

    const int p = blockIdx.x * 256 + tid;
    if (p < N_PAIRS) {
        // invert start(i) = i*(255-i)/2 via sqrt + integer fixup
        float fi = (255.0f - sqrtf(65025.0f - 8.0f * (float)p)) * 0.5f;
        int i = (int)fi;
        if (i > 126) i = 126;
        if (i < 0) i = 0;
        while (i * (255 - i) / 2 > p) --i;
        while ((i + 1) * (254 - i) / 2 <= p) ++i;
        int j = p - i * (255 - i) / 2 + i + 1;

        float w = fmaxf(wint[p], fmaxf(-s_wc[i], -s_wc[j]));
        g_w[N_CRIT + p] = w;
        local += w;
    }

    // block reduce -> one atomicAdd per block
    s_red[tid] = local;
    __syncthreads();
    #pragma unroll
    for (int off = 128; off > 0; off >>= 1) {
        if (tid < off) s_red[tid] += s_red[tid + off];
        __syncthreads();
    }
    if (tid == 0) atomicAdd(&g_sum, s_red[0]);
}

// ---------------------------------------------------------------------------
// GEMV: 512 threads (16 warps). 8 rows per block, 2 warps per row (each warp
// streams one half-row of 1032 float4). Weights staged in smem once per block.
// grid = BATCH / 8 = 2048 blocks; __launch_bounds__(512,4) -> regs<=32, 64 w/SM.
// ---------------------------------------------------------------------------
__global__ __launch_bounds__(THREADS, 4)
void choquet_gemv_kernel(const float* __restrict__ x,
                         const float* __restrict__ thr,
                         float* __restrict__ out) {
    __shared__ __align__(16) float s_w[N_TOT];   // 33 KB
    __shared__ float s_part[16];                 // per-warp partials

    const int tid = threadIdx.x;

    // stage weights (coalesced float4), no sum needed
    const float4* gw4 = reinterpret_cast<const float4*>(g_w);
    float4* sw4 = reinterpret_cast<float4*>(s_w);
    #pragma unroll
    for (int k = tid; k < N_VEC4; k += THREADS) {
        sw4[k] = gw4[k];
    }
    __syncthreads();

    const int warp = tid >> 5;
    const int lane = tid & 31;
    const int row_local = warp >> 1;          // 0..7
    const int half      = warp & 1;           // 0 or 1
    const int row  = blockIdx.x * ROWS_PER_BLOCK + row_local;

    const float4* xr = reinterpret_cast<const float4*>(x + (size_t)row * N_TOT);

    float acc = 0.0f;
    int k = half * N_HALF4 + lane;
    // 1032 float4 / 32 lanes = 32 full iterations + tail of 8
    #pragma unroll 4
    for (int it = 0; it < 32; ++it, k += 32) {
        float4 a = __ldcs(&xr[k]);       // streaming: read-once
        float4 b = sw4[k];
        acc = fmaf(a.x, b.x, acc);
        acc = fmaf(a.y, b.y, acc);
        acc = fmaf(a.z, b.z, acc);
        acc = fmaf(a.w, b.w, acc);
    }
    if (lane < 8) {                      // k = half*1032 + 1024 + lane
        float4 a = __ldcs(&xr[k]);
        float4 b = sw4[k];
        acc = fmaf(a.x, b.x, acc);
        acc = fmaf(a.y, b.y, acc);
        acc = fmaf(a.z, b.z, acc);
        acc = fmaf(a.w, b.w, acc);
    }

    // warp reduce
    #pragma unroll
    for (int off = 16; off > 0; off >>= 1) {
        acc += __shfl_xor_sync(0xFFFFFFFFu, acc, off);
    }
    if (lane == 0) s_part[warp] = acc;
    __syncthreads();

    // combine the two half-row partials and finish
    if (tid < ROWS_PER_BLOCK) {
        float dot = s_part[2 * tid] + s_part[2 * tid + 1];
        float score = dot / g_sum - thr[0];
        out[blockIdx.x * ROWS_PER_BLOCK + tid] = 1.0f / (1.0f + expf(-score));
    }
}

// ---------------------------------------------------------------------------
extern "C" void kernel_launch(void* const* d_in, const int* in_sizes, int n_in,
                              void* d_out, int out_size) {
    const float* x    = (const float*)d_in[0];
    const float* wc   = (const float*)d_in[1];
    const float* wint = (const float*)d_in[2];
    const float* thr  = (const float*)d_in[3];
    float* out = (float*)d_out;

    // zero the weight-sum accumulator (memset node, graph-capturable)
    void* sum_addr = nullptr;
    cudaGetSymbolAddress(&sum_addr, g_sum);
    cudaMemsetAsync(sum_addr, 0, sizeof(float));

    prep_weights_kernel<<<32, 256>>>(wc, wint);
    choquet_gemv_kernel<<<BATCH / ROWS_PER_BLOCK, THREADS>>>(x, thr, out);
}

// round 8
// speedup vs baseline: 1.0121x; 1.0121x over previous
#include <cuda_runtime.h>
#include <math.h>

#define N_CRIT   128
#define N_PAIRS  8128          // 128*127/2
#define N_TOT    8256          // N_CRIT + N_PAIRS
#define N_VEC4   2064          // N_TOT / 4
#define BATCH    16384
#define MIN_W    1e-7f
#define THREADS  512
#define GRID     608           // 152 SMs x 4 resident blocks: one wave, persistent
#define CHUNK4   129           // float4 per warp per row (16 warps x 129 = 2064)
#define MAX_ROWS 27            // ceil(16384 / 608)

__device__ float g_w[N_TOT];   // constrained weights (wc_eff ‖ wint_eff)

// ---------------------------------------------------------------------------
// Prep: one pair per thread. grid = 32 x 256 (8192 >= 8128).
// ---------------------------------------------------------------------------
__global__ __launch_bounds__(256)
void prep_weights_kernel(const float* __restrict__ wc,
                         const float* __restrict__ wint) {
    __shared__ float s_wc[N_CRIT];

    const int tid = threadIdx.x;
    if (tid < N_CRIT) {
        float w = wc[tid];
        w = (w < 0.0f) ? MIN_W : w;
        s_wc[tid] = w;
        if (blockIdx.x == 0) g_w[tid] = w;
    }
    __syncthreads();

    const int p = blockIdx.x * 256 + tid;
    if (p < N_PAIRS) {
        // invert start(i) = i*(255-i)/2 via sqrt + integer fixup
        float fi = (255.0f - sqrtf(65025.0f - 8.0f * (float)p)) * 0.5f;
        int i = (int)fi;
        if (i > 126) i = 126;
        if (i < 0) i = 0;
        while (i * (255 - i) / 2 > p) --i;
        while ((i + 1) * (254 - i) / 2 <= p) ++i;
        int j = p - i * (255 - i) / 2 + i + 1;

        g_w[N_CRIT + p] = fmaxf(wint[p], fmaxf(-s_wc[i], -s_wc[j]));
    }
}

// ---------------------------------------------------------------------------
// Persistent GEMV: 608 blocks x 512 threads. Each block strides rows by 608.
// Warp w owns float4 chunk [129w, 129w+129) of every row; no block barriers
// inside the row loop. One sync at the end, then partial combine.
// ---------------------------------------------------------------------------
__global__ __launch_bounds__(THREADS, 4)
void choquet_gemv_kernel(const float* __restrict__ x,
                         const float* __restrict__ thr,
                         float* __restrict__ out) {
    __shared__ __align__(16) float s_w[N_TOT];       // 33 KB
    __shared__ float s_part[MAX_ROWS][16];           // per-(row,warp) partials
    __shared__ float s_red[THREADS];
    __shared__ float s_inv;

    const int tid = threadIdx.x;

    // stage weights once (coalesced float4) + weight sum
    const float4* gw4 = reinterpret_cast<const float4*>(g_w);
    float4* sw4 = reinterpret_cast<float4*>(s_w);
    float wsum = 0.0f;
    #pragma unroll
    for (int k = tid; k < N_VEC4; k += THREADS) {
        float4 v = gw4[k];
        sw4[k] = v;
        wsum += v.x + v.y + v.z + v.w;
    }
    s_red[tid] = wsum;
    __syncthreads();
    #pragma unroll
    for (int off = THREADS / 2; off > 0; off >>= 1) {
        if (tid < off) s_red[tid] += s_red[tid + off];
        __syncthreads();
    }
    if (tid == 0) s_inv = 1.0f / s_red[0];
    __syncthreads();

    const int warp = tid >> 5;
    const int lane = tid & 31;
    const int kbase = warp * CHUNK4 + lane;          // this warp's chunk start

    // preload this warp's weight chunk into registers? chunk too big; read smem.
    const size_t row_stride4 = N_TOT / 4;            // 2064 float4 per row

    const float4* xr = reinterpret_cast<const float4*>(x) +
                       (size_t)blockIdx.x * row_stride4;
    const size_t step4 = (size_t)GRID * row_stride4;

    int idx = 0;
    for (int row = blockIdx.x; row < BATCH; row += GRID, xr += step4, ++idx) {
        float acc = 0.0f;
        int k = kbase;
        #pragma unroll
        for (int it = 0; it < 4; ++it, k += 32) {    // 4 x 32 = 128 float4
            float4 a = __ldcs(&xr[k]);
            float4 b = sw4[k];
            acc = fmaf(a.x, b.x, acc);
            acc = fmaf(a.y, b.y, acc);
            acc = fmaf(a.z, b.z, acc);
            acc = fmaf(a.w, b.w, acc);
        }
        if (lane == 0) {                             // 129th float4 of the chunk
            float4 a = __ldcs(&xr[k]);
            float4 b = sw4[k];
            acc = fmaf(a.x, b.x, acc);
            acc = fmaf(a.y, b.y, acc);
            acc = fmaf(a.z, b.z, acc);
            acc = fmaf(a.w, b.w, acc);
        }

        // warp reduce
        #pragma unroll
        for (int off = 16; off > 0; off >>= 1) {
            acc += __shfl_xor_sync(0xFFFFFFFFu, acc, off);
        }
        if (lane == 0) s_part[idx][warp] = acc;
    }

    __syncthreads();   // all warps done with all their rows

    // combine 16 partials per local row; thread r handles local row r
    const int nrows = idx;   // same for all warps in block
    if (tid < nrows) {
        float dot = 0.0f;
        #pragma unroll
        for (int w = 0; w < 16; ++w) dot += s_part[tid][w];
        float score = dot * s_inv - thr[0];
        out[blockIdx.x + tid * GRID] = 1.0f / (1.0f + expf(-score));
    }
}

// ---------------------------------------------------------------------------
extern "C" void kernel_launch(void* const* d_in, const int* in_sizes, int n_in,
                              void* d_out, int out_size) {
    const float* x    = (const float*)d_in[0];
    const float* wc   = (const float*)d_in[1];
    const float* wint = (const float*)d_in[2];
    const float* thr  = (const float*)d_in[3];
    float* out = (float*)d_out;

    prep_weights_kernel<<<32, 256>>>(wc, wint);
    choquet_gemv_kernel<<<GRID, THREADS>>>(x, thr, out);
}